// round 15
// baseline (speedup 1.0000x reference)
#include <cuda_runtime.h>
#include <cstddef>

// Problem constants
constexpr int B      = 2;
constexpr int H      = 64;
constexpr int W      = 64;
constexpr int C      = 128;
constexpr int NPOOL  = (H/2) * (W/2) * C; // 131072
constexpr int NOUT   = 32;
constexpr long long NIN = (long long)H * W * C;        // 524288
constexpr long long WZ  = (long long)B * NIN * NOUT;   // 33554432 elems per w_zero tensor

// Output layout (flattened tuple):
//   [0, WZ)             : w_zero (upper)
//   [WZ, WZ+64)         : b_out_u_ (B,1,32)
//   [WZ+64, 2WZ+64)     : w_zero (lower)
//   [2WZ+64, 2WZ+128)   : b_out_l_ (B,1,32)
constexpr long long OFF_BU   = WZ;
constexpr long long OFF_BL   = 2 * WZ + 64;
constexpr long long OUT_ELEM = 2 * WZ + 128;

constexpr int TILE_P  = 1024;             // pool positions per block
constexpr int NCHPB   = NPOOL / TILE_P;   // 128 chunks per batch
constexpr int NRED    = B * NCHPB;        // 256 blocks -> single wave at 2 CTA/SM
constexpr int THREADS = 256;
constexpr int NWARP   = THREADS / 32;     // 8

__device__ float g_su[NRED * NOUT];
__device__ float g_sl[NRED * NOUT];
__device__ unsigned int g_done = 0;

// w * (w>0 ? pu : pl) accumulated into a float4
#define ACC4(acc, v, pu, pl)                                       \
    do {                                                           \
        (acc).x = fmaf((v).x, (v).x > 0.f ? (pu) : (pl), (acc).x); \
        (acc).y = fmaf((v).y, (v).y > 0.f ? (pu) : (pl), (acc).y); \
        (acc).z = fmaf((v).z, (v).z > 0.f ? (pu) : (pl), (acc).z); \
        (acc).w = fmaf((v).w, (v).w > 0.f ? (pu) : (pl), (acc).w); \
    } while (0)

__device__ __forceinline__ float4 fmax4(float4 a, float4 b) {
    return make_float4(fmaxf(a.x, b.x), fmaxf(a.y, b.y),
                       fmaxf(a.z, b.z), fmaxf(a.w, b.w));
}

__global__ __launch_bounds__(THREADS, 2)
void reduce_kernel(const float* __restrict__ uc,
                   const float* __restrict__ lc,
                   const float* __restrict__ wu,
                   const float* __restrict__ wl,
                   const float* __restrict__ bu_bias,
                   const float* __restrict__ bl_bias,
                   float* __restrict__ out)
{
    __shared__ float s_bu[TILE_P];
    __shared__ float s_bl[TILE_P];
    __shared__ float r_u[NWARP][NOUT];
    __shared__ float r_l[NWARP][NOUT];

    const int t     = threadIdx.x;
    const int blk   = blockIdx.x;
    const int chunk = blk & (NCHPB - 1);
    const int b     = blk >> 7;            // NCHPB == 128
    const int p0    = chunk * TILE_P;

    // ---- Phase 1: vectorized 2x2 maxpool (4 channels per thread) ----
    // Pool position p = p0 + 4*g + cc; group g covers channels [4g & 127 .. +3]
    // at one (ph, pw). 8 x LDG.128 per thread (128 B in flight).
    {
        const int g  = t;                   // 0..255 float4 groups (TILE_P/4)
        const int p  = p0 + g * 4;
        const int c4 = g & (C / 4 - 1);     // float4 index within channel row
        const int pw = (p >> 7) & 31;
        const int ph = p >> 12;
        const size_t row4 = ((size_t)(2 * ph) * W + 2 * pw) * (C / 4) + c4;
        const float4* uc4 = reinterpret_cast<const float4*>(uc) + (size_t)b * (NIN / 4);
        const float4* lc4 = reinterpret_cast<const float4*>(lc) + (size_t)b * (NIN / 4);
        // neighbors: +0, +C (=+32 f4), +W*C (=+2048 f4), +W*C+C
        const float4 u0 = uc4[row4];
        const float4 u1 = uc4[row4 + C / 4];
        const float4 u2 = uc4[row4 + W * C / 4];
        const float4 u3 = uc4[row4 + W * C / 4 + C / 4];
        const float4 l0 = lc4[row4];
        const float4 l1 = lc4[row4 + C / 4];
        const float4 l2 = lc4[row4 + W * C / 4];
        const float4 l3 = lc4[row4 + W * C / 4 + C / 4];
        reinterpret_cast<float4*>(s_bu)[g] = fmax4(fmax4(u0, u1), fmax4(u2, u3));
        reinterpret_cast<float4*>(s_bl)[g] = fmax4(fmax4(l0, l1), fmax4(l2, l3));
    }
    __syncthreads();

    // ---- Phase 2: deep-MLP vectorized reduction (identical to R13 best) ----
    const int warp  = t >> 5;
    const int lane  = t & 31;
    const int psub  = lane >> 3;
    const int j4f   = lane & 7;
    const int posb  = warp * 4 + psub;            // position within a 32-group
    const int tbase = posb * 8 + j4f;             // float4 index within group

    const float4* wu4 = reinterpret_cast<const float4*>(
        wu + ((size_t)b * NPOOL + p0) * NOUT);
    const float4* wl4 = reinterpret_cast<const float4*>(
        wl + ((size_t)b * NPOOL + p0) * NOUT);

    float4 au0 = {0,0,0,0}, au1 = {0,0,0,0};
    float4 al0 = {0,0,0,0}, al1 = {0,0,0,0};

    #pragma unroll
    for (int it8 = 0; it8 < TILE_P / 256; ++it8) {  // 4 batches of 8 iterations
        const int i0 = it8 * 2048 + tbase;          // 8 iterations x 256 float4s
        const float4 u0 = wu4[i0];
        const float4 u1 = wu4[i0 + 256];
        const float4 u2 = wu4[i0 + 512];
        const float4 u3 = wu4[i0 + 768];
        const float4 u4 = wu4[i0 + 1024];
        const float4 u5 = wu4[i0 + 1280];
        const float4 u6 = wu4[i0 + 1536];
        const float4 u7 = wu4[i0 + 1792];
        const float4 v0 = wl4[i0];
        const float4 v1 = wl4[i0 + 256];
        const float4 v2 = wl4[i0 + 512];
        const float4 v3 = wl4[i0 + 768];
        const float4 v4 = wl4[i0 + 1024];
        const float4 v5 = wl4[i0 + 1280];
        const float4 v6 = wl4[i0 + 1536];
        const float4 v7 = wl4[i0 + 1792];

        const int pb = it8 * 256 + posb;            // 8 iterations x 32 positions
        const float pu0 = s_bu[pb],       pl0 = s_bl[pb];
        const float pu1 = s_bu[pb + 32],  pl1 = s_bl[pb + 32];
        const float pu2 = s_bu[pb + 64],  pl2 = s_bl[pb + 64];
        const float pu3 = s_bu[pb + 96],  pl3 = s_bl[pb + 96];
        const float pu4 = s_bu[pb + 128], pl4 = s_bl[pb + 128];
        const float pu5 = s_bu[pb + 160], pl5 = s_bl[pb + 160];
        const float pu6 = s_bu[pb + 192], pl6 = s_bl[pb + 192];
        const float pu7 = s_bu[pb + 224], pl7 = s_bl[pb + 224];

        ACC4(au0, u0, pu0, pl0);
        ACC4(au1, u1, pu1, pl1);
        ACC4(au0, u2, pu2, pl2);
        ACC4(au1, u3, pu3, pl3);
        ACC4(au0, u4, pu4, pl4);
        ACC4(au1, u5, pu5, pl5);
        ACC4(au0, u6, pu6, pl6);
        ACC4(au1, u7, pu7, pl7);
        ACC4(al0, v0, pl0, pu0);
        ACC4(al1, v1, pl1, pu1);
        ACC4(al0, v2, pl2, pu2);
        ACC4(al1, v3, pl3, pu3);
        ACC4(al0, v4, pl4, pu4);
        ACC4(al1, v5, pl5, pu5);
        ACC4(al0, v6, pl6, pu6);
        ACC4(al1, v7, pl7, pu7);
    }

    float4 au = make_float4(au0.x + au1.x, au0.y + au1.y,
                            au0.z + au1.z, au0.w + au1.w);
    float4 al = make_float4(al0.x + al1.x, al0.y + al1.y,
                            al0.z + al1.z, al0.w + al1.w);

    // Reduce 4 position sub-slots (lanes differing in bits 3,4)
    #pragma unroll
    for (int off = 8; off <= 16; off <<= 1) {
        au.x += __shfl_xor_sync(0xffffffffu, au.x, off);
        au.y += __shfl_xor_sync(0xffffffffu, au.y, off);
        au.z += __shfl_xor_sync(0xffffffffu, au.z, off);
        au.w += __shfl_xor_sync(0xffffffffu, au.w, off);
        al.x += __shfl_xor_sync(0xffffffffu, al.x, off);
        al.y += __shfl_xor_sync(0xffffffffu, al.y, off);
        al.z += __shfl_xor_sync(0xffffffffu, al.z, off);
        al.w += __shfl_xor_sync(0xffffffffu, al.w, off);
    }
    if (lane < 8) {
        *reinterpret_cast<float4*>(&r_u[warp][j4f * 4]) = au;
        *reinterpret_cast<float4*>(&r_l[warp][j4f * 4]) = al;
    }
    __syncthreads();

    if (warp == 0) {
        float su = 0.0f, sl = 0.0f;
        #pragma unroll
        for (int k = 0; k < NWARP; k++) {
            su += r_u[k][lane];
            sl += r_l[k][lane];
        }
        g_su[blk * NOUT + lane] = su;
        g_sl[blk * NOUT + lane] = sl;
    }

    // ---- Last-block finalize (scratch is L2-hot) ----
    __shared__ bool s_last;
    __threadfence();
    __syncthreads();
    if (t == 0) {
        unsigned int prev = atomicAdd(&g_done, 1u);
        s_last = (prev == (unsigned int)(NRED - 1));
    }
    __syncthreads();
    if (!s_last) return;
    __threadfence();

    {
        const int idx  = t & 127;
        const int half = t >> 7;
        const int bb   = idx >> 6;          // 0..1
        const int ul   = (idx >> 5) & 1;    // 0 = upper, 1 = lower
        const int j    = idx & 31;
        const float* sc = ul ? g_sl : g_su;
        const int k0 = bb * NCHPB + half * (NCHPB / 2);
        float s = 0.0f;
        #pragma unroll 8
        for (int k = 0; k < NCHPB / 2; k++)
            s += sc[(k0 + k) * NOUT + j];

        __shared__ float s_part[128];
        if (half == 1) s_part[idx] = s;
        __syncthreads();
        if (half == 0) {
            s += s_part[idx];
            const float bias = ul ? bl_bias[bb * NOUT + j] : bu_bias[bb * NOUT + j];
            const long long off = ul ? OFF_BL : OFF_BU;
            out[off + bb * NOUT + j] = s + bias;
        }
        if (t == 0) g_done = 0;   // reset for next graph replay
    }
}

extern "C" void kernel_launch(void* const* d_in, const int* in_sizes, int n_in,
                              void* d_out, int out_size)
{
    // metadata order: y, x_0, u_c, l_c, w_out_u, b_out_u, w_out_l, b_out_l
    const float* uc = (const float*)d_in[2];
    const float* lc = (const float*)d_in[3];
    const float* wu = (const float*)d_in[4];
    const float* bu = (const float*)d_in[5];
    const float* wl = (const float*)d_in[6];
    const float* bl = (const float*)d_in[7];
    float* out = (float*)d_out;

    // One contiguous memset over the ENTIRE output (incl. bias slots), then
    // the reduce overwrites the 128 bias floats.
    cudaMemsetAsync(out, 0, (size_t)OUT_ELEM * sizeof(float));
    reduce_kernel<<<NRED, THREADS>>>(uc, lc, wu, wl, bu, bl, out);
}

// round 16
// speedup vs baseline: 1.1243x; 1.1243x over previous
#include <cuda_runtime.h>
#include <cstddef>

// Problem constants
constexpr int B      = 2;
constexpr int H      = 64;
constexpr int W      = 64;
constexpr int C      = 128;
constexpr int NPOOL  = (H/2) * (W/2) * C; // 131072
constexpr int NOUT   = 32;
constexpr long long NIN = (long long)H * W * C;        // 524288
constexpr long long WZ  = (long long)B * NIN * NOUT;   // 33554432 elems per w_zero tensor

// Output layout (flattened tuple):
//   [0, WZ)             : w_zero (upper)
//   [WZ, WZ+64)         : b_out_u_ (B,1,32)
//   [WZ+64, 2WZ+64)     : w_zero (lower)
//   [2WZ+64, 2WZ+128)   : b_out_l_ (B,1,32)
constexpr long long OFF_BU   = WZ;
constexpr long long OFF_W2   = WZ + 64;
constexpr long long OFF_BL   = 2 * WZ + 64;

constexpr int TILE_P  = 1024;             // pool positions per block
constexpr int NCHPB   = NPOOL / TILE_P;   // 128 chunks per batch
constexpr int NRED    = B * NCHPB;        // 256 blocks -> single wave at 2 CTA/SM
constexpr int THREADS = 256;
constexpr int NWARP   = THREADS / 32;     // 8

__device__ float g_su[NRED * NOUT];
__device__ float g_sl[NRED * NOUT];
__device__ unsigned int g_done = 0;

// w * (w>0 ? pu : pl) accumulated into a float4
#define ACC4(acc, v, pu, pl)                                       \
    do {                                                           \
        (acc).x = fmaf((v).x, (v).x > 0.f ? (pu) : (pl), (acc).x); \
        (acc).y = fmaf((v).y, (v).y > 0.f ? (pu) : (pl), (acc).y); \
        (acc).z = fmaf((v).z, (v).z > 0.f ? (pu) : (pl), (acc).z); \
        (acc).w = fmaf((v).w, (v).w > 0.f ? (pu) : (pl), (acc).w); \
    } while (0)

__device__ __forceinline__ float4 fmax4(float4 a, float4 b) {
    return make_float4(fmaxf(a.x, b.x), fmaxf(a.y, b.y),
                       fmaxf(a.z, b.z), fmaxf(a.w, b.w));
}

__global__ __launch_bounds__(THREADS, 2)
void reduce_kernel(const float* __restrict__ uc,
                   const float* __restrict__ lc,
                   const float* __restrict__ wu,
                   const float* __restrict__ wl,
                   const float* __restrict__ bu_bias,
                   const float* __restrict__ bl_bias,
                   float* __restrict__ out)
{
    __shared__ float s_bu[TILE_P];
    __shared__ float s_bl[TILE_P];
    __shared__ float r_u[NWARP][NOUT];
    __shared__ float r_l[NWARP][NOUT];

    const int t     = threadIdx.x;
    const int blk   = blockIdx.x;
    const int chunk = blk & (NCHPB - 1);
    const int b     = blk >> 7;            // NCHPB == 128
    const int p0    = chunk * TILE_P;

    // ---- Phase 1: vectorized 2x2 maxpool (4 channels per thread) ----
    {
        const int g  = t;                   // 0..255 float4 groups (TILE_P/4)
        const int p  = p0 + g * 4;
        const int c4 = g & (C / 4 - 1);
        const int pw = (p >> 7) & 31;
        const int ph = p >> 12;
        const size_t row4 = ((size_t)(2 * ph) * W + 2 * pw) * (C / 4) + c4;
        const float4* uc4 = reinterpret_cast<const float4*>(uc) + (size_t)b * (NIN / 4);
        const float4* lc4 = reinterpret_cast<const float4*>(lc) + (size_t)b * (NIN / 4);
        const float4 u0 = uc4[row4];
        const float4 u1 = uc4[row4 + C / 4];
        const float4 u2 = uc4[row4 + W * C / 4];
        const float4 u3 = uc4[row4 + W * C / 4 + C / 4];
        const float4 l0 = lc4[row4];
        const float4 l1 = lc4[row4 + C / 4];
        const float4 l2 = lc4[row4 + W * C / 4];
        const float4 l3 = lc4[row4 + W * C / 4 + C / 4];
        reinterpret_cast<float4*>(s_bu)[g] = fmax4(fmax4(u0, u1), fmax4(u2, u3));
        reinterpret_cast<float4*>(s_bl)[g] = fmax4(fmax4(l0, l1), fmax4(l2, l3));
    }
    __syncthreads();

    // ---- Phase 2: deep-MLP vectorized reduction (R13 best) ----
    const int warp  = t >> 5;
    const int lane  = t & 31;
    const int psub  = lane >> 3;
    const int j4f   = lane & 7;
    const int posb  = warp * 4 + psub;
    const int tbase = posb * 8 + j4f;

    const float4* wu4 = reinterpret_cast<const float4*>(
        wu + ((size_t)b * NPOOL + p0) * NOUT);
    const float4* wl4 = reinterpret_cast<const float4*>(
        wl + ((size_t)b * NPOOL + p0) * NOUT);

    float4 au0 = {0,0,0,0}, au1 = {0,0,0,0};
    float4 al0 = {0,0,0,0}, al1 = {0,0,0,0};

    #pragma unroll
    for (int it8 = 0; it8 < TILE_P / 256; ++it8) {
        const int i0 = it8 * 2048 + tbase;
        const float4 u0 = wu4[i0];
        const float4 u1 = wu4[i0 + 256];
        const float4 u2 = wu4[i0 + 512];
        const float4 u3 = wu4[i0 + 768];
        const float4 u4 = wu4[i0 + 1024];
        const float4 u5 = wu4[i0 + 1280];
        const float4 u6 = wu4[i0 + 1536];
        const float4 u7 = wu4[i0 + 1792];
        const float4 v0 = wl4[i0];
        const float4 v1 = wl4[i0 + 256];
        const float4 v2 = wl4[i0 + 512];
        const float4 v3 = wl4[i0 + 768];
        const float4 v4 = wl4[i0 + 1024];
        const float4 v5 = wl4[i0 + 1280];
        const float4 v6 = wl4[i0 + 1536];
        const float4 v7 = wl4[i0 + 1792];

        const int pb = it8 * 256 + posb;
        const float pu0 = s_bu[pb],       pl0 = s_bl[pb];
        const float pu1 = s_bu[pb + 32],  pl1 = s_bl[pb + 32];
        const float pu2 = s_bu[pb + 64],  pl2 = s_bl[pb + 64];
        const float pu3 = s_bu[pb + 96],  pl3 = s_bl[pb + 96];
        const float pu4 = s_bu[pb + 128], pl4 = s_bl[pb + 128];
        const float pu5 = s_bu[pb + 160], pl5 = s_bl[pb + 160];
        const float pu6 = s_bu[pb + 192], pl6 = s_bl[pb + 192];
        const float pu7 = s_bu[pb + 224], pl7 = s_bl[pb + 224];

        ACC4(au0, u0, pu0, pl0);
        ACC4(au1, u1, pu1, pl1);
        ACC4(au0, u2, pu2, pl2);
        ACC4(au1, u3, pu3, pl3);
        ACC4(au0, u4, pu4, pl4);
        ACC4(au1, u5, pu5, pl5);
        ACC4(au0, u6, pu6, pl6);
        ACC4(au1, u7, pu7, pl7);
        ACC4(al0, v0, pl0, pu0);
        ACC4(al1, v1, pl1, pu1);
        ACC4(al0, v2, pl2, pu2);
        ACC4(al1, v3, pl3, pu3);
        ACC4(al0, v4, pl4, pu4);
        ACC4(al1, v5, pl5, pu5);
        ACC4(al0, v6, pl6, pu6);
        ACC4(al1, v7, pl7, pu7);
    }

    float4 au = make_float4(au0.x + au1.x, au0.y + au1.y,
                            au0.z + au1.z, au0.w + au1.w);
    float4 al = make_float4(al0.x + al1.x, al0.y + al1.y,
                            al0.z + al1.z, al0.w + al1.w);

    #pragma unroll
    for (int off = 8; off <= 16; off <<= 1) {
        au.x += __shfl_xor_sync(0xffffffffu, au.x, off);
        au.y += __shfl_xor_sync(0xffffffffu, au.y, off);
        au.z += __shfl_xor_sync(0xffffffffu, au.z, off);
        au.w += __shfl_xor_sync(0xffffffffu, au.w, off);
        al.x += __shfl_xor_sync(0xffffffffu, al.x, off);
        al.y += __shfl_xor_sync(0xffffffffu, al.y, off);
        al.z += __shfl_xor_sync(0xffffffffu, al.z, off);
        al.w += __shfl_xor_sync(0xffffffffu, al.w, off);
    }
    if (lane < 8) {
        *reinterpret_cast<float4*>(&r_u[warp][j4f * 4]) = au;
        *reinterpret_cast<float4*>(&r_l[warp][j4f * 4]) = al;
    }
    __syncthreads();

    if (warp == 0) {
        float su = 0.0f, sl = 0.0f;
        #pragma unroll
        for (int k = 0; k < NWARP; k++) {
            su += r_u[k][lane];
            sl += r_l[k][lane];
        }
        g_su[blk * NOUT + lane] = su;
        g_sl[blk * NOUT + lane] = sl;
    }

    // ---- Last-block finalize (scratch is L2-hot) ----
    __shared__ bool s_last;
    __threadfence();
    __syncthreads();
    if (t == 0) {
        unsigned int prev = atomicAdd(&g_done, 1u);
        s_last = (prev == (unsigned int)(NRED - 1));
    }
    __syncthreads();
    if (!s_last) return;
    __threadfence();

    {
        const int idx  = t & 127;
        const int half = t >> 7;
        const int bb   = idx >> 6;          // 0..1
        const int ul   = (idx >> 5) & 1;    // 0 = upper, 1 = lower
        const int j    = idx & 31;
        const float* sc = ul ? g_sl : g_su;
        const int k0 = bb * NCHPB + half * (NCHPB / 2);
        float s = 0.0f;
        #pragma unroll 8
        for (int k = 0; k < NCHPB / 2; k++)
            s += sc[(k0 + k) * NOUT + j];

        __shared__ float s_part[128];
        if (half == 1) s_part[idx] = s;
        __syncthreads();
        if (half == 0) {
            s += s_part[idx];
            const float bias = ul ? bl_bias[bb * NOUT + j] : bu_bias[bb * NOUT + j];
            const long long off = ul ? OFF_BL : OFF_BU;
            out[off + bb * NOUT + j] = s + bias;
        }
        if (t == 0) g_done = 0;   // reset for next graph replay
    }
}

extern "C" void kernel_launch(void* const* d_in, const int* in_sizes, int n_in,
                              void* d_out, int out_size)
{
    // metadata order: y, x_0, u_c, l_c, w_out_u, b_out_u, w_out_l, b_out_l
    const float* uc = (const float*)d_in[2];
    const float* lc = (const float*)d_in[3];
    const float* wu = (const float*)d_in[4];
    const float* bu = (const float*)d_in[5];
    const float* wl = (const float*)d_in[6];
    const float* bl = (const float*)d_in[7];
    float* out = (float*)d_out;

    // Side stream + events, created once (host-side resources only; no device
    // memory). Graph capture records the cross-stream dependencies so the
    // memset fills run CONCURRENTLY with the read-bound reduce.
    static cudaStream_t s_aux = nullptr;
    static cudaEvent_t  e_fork = nullptr, e_join = nullptr;
    if (s_aux == nullptr) {
        cudaStreamCreateWithFlags(&s_aux, cudaStreamNonBlocking);
        cudaEventCreateWithFlags(&e_fork, cudaEventDisableTiming);
        cudaEventCreateWithFlags(&e_join, cudaEventDisableTiming);
    }

    // Fork: aux stream joins the capture after the fork event.
    cudaEventRecord(e_fork, (cudaStream_t)0);
    cudaStreamWaitEvent(s_aux, e_fork, 0);

    // Writes on aux stream: the two w_zero regions, EXCLUDING bias slots
    // (no race with the reduce's finalize writes).
    cudaMemsetAsync(out,          0, (size_t)WZ * sizeof(float), s_aux);
    cudaMemsetAsync(out + OFF_W2, 0, (size_t)WZ * sizeof(float), s_aux);
    cudaEventRecord(e_join, s_aux);

    // Reads + bias writes on the main (capture) stream, concurrent with fills.
    reduce_kernel<<<NRED, THREADS>>>(uc, lc, wu, wl, bu, bl, out);

    // Join: graph end depends on both streams.
    cudaStreamWaitEvent((cudaStream_t)0, e_join, 0);
}